// round 17
// baseline (speedup 1.0000x reference)
#include <cuda_runtime.h>
#include <math.h>

#define N_NODES 100000
#define N_EDGES 1200000
#define KP1 4096
#define KP2 256
#define NEG 0.01f
#define RCAP 8192

// ---- device scratch. INVARIANT: accumulator arrays return to ZERO by the end
// of each kernel_launch (cleanup fused into k_fc); first call uses CUDA zero-init.
__device__ float  g_deg[N_NODES];        // cleaned
__device__ float  g_dinv[N_NODES];       // overwritten
__device__ float4 g_P4[N_NODES];         // overwritten
__device__ float4 g_agg4[N_NODES];       // cleaned
__device__ float  g_score1[N_NODES];     // overwritten
__device__ int    g_map0[N_NODES];       // cleaned (0 = dropped)
__device__ int    g_rk[N_NODES];         // rank partial counts (cleaned)
__device__ unsigned g_hist16[65536];     // cleaned
__device__ unsigned g_gsum[256];         // overwritten
__device__ unsigned g_thresh;            // overwritten
__device__ int    g_ccount;              // cleaned
__device__ int    g_cand[N_NODES];
__device__ float  g_x1p[KP1 * 64];       // overwritten
__device__ int2   g_e2[N_EDGES];
__device__ int    g_e2cnt;               // cleaned
__device__ float  g_deg2x[KP1];          // cleaned
__device__ float  g_agg64[KP1 * 64];     // cleaned
__device__ float  g_x2[KP1 * 128];       // overwritten
__device__ float  g_agg128[KP1 * 128];   // cleaned
__device__ float  g_x3[KP1 * 256];       // overwritten
__device__ float  g_score2[KP1];         // overwritten
__device__ int    g_rk2[KP1];            // cleaned
__device__ int    g_perm2[KP2];          // overwritten
__device__ float  g_sc2[KP2];            // overwritten
__device__ float4 g_W1p[64];             // packed {W1r0,r1,r2,b1} (overwritten)
__device__ float  g_invn1, g_invn2;      // overwritten

__device__ __forceinline__ unsigned f2u(float f) {
    unsigned u = __float_as_uint(f);
    return (u & 0x80000000u) ? ~u : (u | 0x80000000u);
}
__device__ __forceinline__ float lrelu(float h) { return (h < 0.f) ? NEG * h : h; }

// ---------------- kernels ----------------

// #1: in-degree from dst column only (int2 loads: 2 edges/thread)
__global__ void k_edge_deg(const int* __restrict__ ei) {
    int e2 = blockIdx.x * blockDim.x + threadIdx.x;
    if (e2 < N_EDGES / 2) {
        int2 d = ((const int2*)(ei + N_EDGES))[e2];
        atomicAdd(&g_deg[d.x], 1.0f);
        atomicAdd(&g_deg[d.y], 1.0f);
    }
}

// #2: dinv, P4 = pos*dinv; packed W1; out = fcb; norms
__global__ void k_prep(const float* __restrict__ pos, const float* __restrict__ W1,
                       const float* __restrict__ b1, const float* __restrict__ p1,
                       const float* __restrict__ p2, const float* __restrict__ fcb,
                       float* __restrict__ out) {
    int n = blockIdx.x * blockDim.x + threadIdx.x;
    if (n < N_NODES) {
        float di = rsqrtf(g_deg[n] + 1.0f);
        g_dinv[n] = di;
        g_P4[n] = make_float4(pos[3 * n] * di, pos[3 * n + 1] * di,
                              pos[3 * n + 2] * di, 0.f);
    }
    if (n < 64) g_W1p[n] = make_float4(W1[n], W1[64 + n], W1[128 + n], b1[n]);
    if (n < 512) out[n] = fcb[n];
    if (n == 0) {
        float s = 0.f;
        for (int j = 0; j < 64; j++) s += p1[j] * p1[j];
        g_invn1 = 1.0f / sqrtf(s);
        s = 0.f;
        for (int j = 0; j < 256; j++) s += p2[j] * p2[j];
        g_invn2 = 1.0f / sqrtf(s);
    }
}

// #3: agg4[d] += P4[s]
__global__ void k_agg3(const int* __restrict__ ei) {
    int e = blockIdx.x * blockDim.x + threadIdx.x;
    if (e < N_EDGES) {
        atomicAdd(&g_agg4[ei[N_EDGES + e]], g_P4[ei[e]]);
    }
}

// #4 (profiled): score1, WARP-PER-NODE. Lane L covers features L and L+32;
// warp-reduce the p1-dot. 100k warps => TLP-rich, short serial chain.
__global__ void k_score1(const float* __restrict__ p1) {
    __shared__ float4 sWp[64];
    __shared__ float sp[64];
    if (threadIdx.x < 64) { sWp[threadIdx.x] = g_W1p[threadIdx.x]; sp[threadIdx.x] = p1[threadIdx.x]; }
    __syncthreads();
    int gw = (blockIdx.x * blockDim.x + threadIdx.x) >> 5;
    int lane = threadIdx.x & 31;
    if (gw < N_NODES) {
        float di = g_dinv[gw];
        float4 a = g_agg4[gw];
        float4 p = g_P4[gw];
        float q0 = di * (a.x + p.x);
        float q1 = di * (a.y + p.y);
        float q2 = di * (a.z + p.z);
        float4 w0 = sWp[lane];
        float4 w1 = sWp[lane + 32];
        float h0 = q0 * w0.x + q1 * w0.y + q2 * w0.z + w0.w;
        float h1 = q0 * w1.x + q1 * w1.y + q2 * w1.z + w1.w;
        float s = lrelu(h0) * sp[lane] + lrelu(h1) * sp[lane + 32];
        #pragma unroll
        for (int off = 16; off > 0; off >>= 1) s += __shfl_xor_sync(0xFFFFFFFFu, s, off);
        if (lane == 0) {
            float sc = tanhf(s * g_invn1);
            g_score1[gw] = sc;
            atomicAdd(&g_hist16[f2u(sc) >> 16], 1u);
        }
    }
}

// #5: group sums (256 blocks, one bin per thread) — split kernel (launch boundary
// is the cross-block sync; in-kernel election pattern proved unreliable in R13)
__global__ void k_scan_a() {
    __shared__ unsigned sm[256];
    int g = blockIdx.x, t = threadIdx.x;
    sm[t] = g_hist16[g * 256 + t];
    __syncthreads();
    for (int off = 128; off > 0; off >>= 1) {
        if (t < off) sm[t] += sm[t + off];
        __syncthreads();
    }
    if (t == 0) g_gsum[g] = sm[0];
}

// #6: pick group, then bin (single block)
__global__ void k_scan_b() {
    __shared__ unsigned sm[768];
    int t = threadIdx.x;
    sm[t] = g_gsum[t];
    __syncthreads();
    if (t == 0) {
        unsigned cum = 0; int gs = 0;
        for (int g = 255; g >= 0; g--) {
            if (cum + sm[g] >= (unsigned)KP1) { gs = g; break; }
            cum += sm[g];
        }
        sm[256] = (unsigned)gs; sm[257] = cum;
    }
    __syncthreads();
    int gs = (int)sm[256];
    sm[512 + t] = g_hist16[gs * 256 + t];
    __syncthreads();
    if (t == 0) {
        unsigned cum = sm[257];
        for (int b = 255; b >= 0; b--) {
            unsigned c = sm[512 + b];
            if (cum + c >= (unsigned)KP1) { g_thresh = (unsigned)(gs * 256 + b); break; }
            cum += c;
        }
    }
}

// #7
__global__ void k_compact() {
    int n = blockIdx.x * blockDim.x + threadIdx.x;
    if (n < N_NODES) {
        if ((f2u(g_score1[n]) >> 16) >= g_thresh) {
            int p = atomicAdd(&g_ccount, 1);
            g_cand[p] = n;
        }
    }
}

// #8: 2D partial rank counts: item (i, chunk) counts uj>ui over chunk of [0,C)
__global__ void k_rank1a() {
    __shared__ unsigned su[RCAP];
    int C = g_ccount;
    int cc = (C < RCAP) ? C : RCAP;
    for (int j = threadIdx.x; j < cc; j += blockDim.x)
        su[j] = f2u(g_score1[g_cand[j]]);
    __syncthreads();
    int total = C * 8;
    int stride = gridDim.x * blockDim.x;
    for (int w = blockIdx.x * blockDim.x + threadIdx.x; w < total; w += stride) {
        int i = w >> 3, ch = w & 7;
        int idx = g_cand[i];
        unsigned u = (i < cc) ? su[i] : f2u(g_score1[idx]);
        int lo = (ch * C) >> 3, hi = ((ch + 1) * C) >> 3;
        int r = 0;
        for (int j = lo; j < hi; j++) {
            unsigned uj = (j < cc) ? su[j] : f2u(g_score1[g_cand[j]]);
            if (uj > u) r++;
            else if (uj == u && j != i) { if (g_cand[j] < idx) r++; }
        }
        if (r) atomicAdd(&g_rk[i], r);
    }
}

// #9: fused placement + x1p row build: candidate i with rank r<KP1 emits row r
__global__ void k_place1() {
    __shared__ float4 sWp[64];
    if (threadIdx.x < 64) sWp[threadIdx.x] = g_W1p[threadIdx.x];
    __syncthreads();
    int C = g_ccount;
    int total = C * 64;
    int stride = gridDim.x * blockDim.x;
    for (int w = blockIdx.x * blockDim.x + threadIdx.x; w < total; w += stride) {
        int i = w >> 6, j = w & 63;
        int r = g_rk[i];
        if (r >= KP1) continue;
        int n = g_cand[i];
        float sc = g_score1[n];
        float di = g_dinv[n];
        float4 a = g_agg4[n];
        float4 p = g_P4[n];
        float q0 = di * (a.x + p.x);
        float q1 = di * (a.y + p.y);
        float q2 = di * (a.z + p.z);
        float4 wv = sWp[j];
        float h = q0 * wv.x + q1 * wv.y + q2 * wv.z + wv.w;
        g_x1p[r * 64 + j] = lrelu(h) * sc;
        if (j == 0) g_map0[n] = r + 1;
    }
}

// #10: surviving edges -> relabeled list + new degree
__global__ void k_ecompact(const int* __restrict__ ei) {
    int e = blockIdx.x * blockDim.x + threadIdx.x;
    if (e < N_EDGES) {
        int ms = g_map0[ei[e]];
        int md = g_map0[ei[N_EDGES + e]];
        if (ms > 0 && md > 0) {
            int p = atomicAdd(&g_e2cnt, 1);
            g_e2[p] = make_int2(ms - 1, md - 1);
            atomicAdd(&g_deg2x[md - 1], 1.0f);
        }
    }
}

// #11
__global__ void k_escat64() {
    int total = g_e2cnt * 64;
    int stride = gridDim.x * blockDim.x;
    for (int t = blockIdx.x * blockDim.x + threadIdx.x; t < total; t += stride) {
        int e = t >> 6, j = t & 63;
        int2 ed = g_e2[e];
        float nm = rsqrtf(1.0f + g_deg2x[ed.x]) * rsqrtf(1.0f + g_deg2x[ed.y]);
        atomicAdd(&g_agg64[ed.y * 64 + j], g_x1p[ed.x * 64 + j] * nm);
    }
}

// #12: x2 = leaky((agg64 + x1p/deg2) @ W2 + b2)
__global__ void __launch_bounds__(128) k_gemm2(const float* __restrict__ W2,
                                               const float* __restrict__ b2) {
    __shared__ float sA[32 * 64];
    int row0 = blockIdx.x * 32;
    int c = threadIdx.x;
    for (int t = threadIdx.x; t < 32 * 64; t += 128) {
        int row = row0 + (t >> 6);
        sA[t] = g_agg64[row0 * 64 + t] + g_x1p[row0 * 64 + t] / (1.0f + g_deg2x[row]);
    }
    __syncthreads();
    float acc[32];
    float bb = b2[c];
    #pragma unroll
    for (int r = 0; r < 32; r++) acc[r] = bb;
    for (int k = 0; k < 64; k++) {
        float w = W2[k * 128 + c];
        #pragma unroll
        for (int r = 0; r < 32; r++) acc[r] += sA[r * 64 + k] * w;
    }
    #pragma unroll
    for (int r = 0; r < 32; r++) g_x2[(row0 + r) * 128 + c] = lrelu(acc[r]);
}

// #13
__global__ void k_escat128() {
    int total = g_e2cnt * 128;
    int stride = gridDim.x * blockDim.x;
    for (int t = blockIdx.x * blockDim.x + threadIdx.x; t < total; t += stride) {
        int e = t >> 7, j = t & 127;
        int2 ed = g_e2[e];
        float nm = rsqrtf(1.0f + g_deg2x[ed.x]) * rsqrtf(1.0f + g_deg2x[ed.y]);
        atomicAdd(&g_agg128[ed.y * 128 + j], g_x2[ed.x * 128 + j] * nm);
    }
}

// #14: x3 = leaky((agg128 + x2/deg2) @ W3 + b3)
__global__ void __launch_bounds__(256) k_gemm3(const float* __restrict__ W3,
                                               const float* __restrict__ b3) {
    __shared__ float sA[16 * 128];
    int row0 = blockIdx.x * 16;
    int c = threadIdx.x;
    for (int t = threadIdx.x; t < 16 * 128; t += 256) {
        int row = row0 + (t >> 7);
        sA[t] = g_agg128[row0 * 128 + t] + g_x2[row0 * 128 + t] / (1.0f + g_deg2x[row]);
    }
    __syncthreads();
    float acc[16];
    float bb = b3[c];
    #pragma unroll
    for (int r = 0; r < 16; r++) acc[r] = bb;
    for (int k = 0; k < 128; k++) {
        float w = W3[k * 256 + c];
        #pragma unroll
        for (int r = 0; r < 16; r++) acc[r] += sA[r * 128 + k] * w;
    }
    #pragma unroll
    for (int r = 0; r < 16; r++) g_x3[(row0 + r) * 256 + c] = lrelu(acc[r]);
}

// #15: score2 (one warp per node)
__global__ void k_score2(const float* __restrict__ p2) {
    __shared__ float sp[256];
    for (int t = threadIdx.x; t < 256; t += blockDim.x) sp[t] = p2[t];
    __syncthreads();
    int gw = (blockIdx.x * blockDim.x + threadIdx.x) >> 5;
    int lane = threadIdx.x & 31;
    if (gw < KP1) {
        float s = 0.f;
        #pragma unroll
        for (int j = lane; j < 256; j += 32) s += g_x3[gw * 256 + j] * sp[j];
        #pragma unroll
        for (int off = 16; off > 0; off >>= 1) s += __shfl_xor_sync(0xFFFFFFFFu, s, off);
        if (lane == 0) g_score2[gw] = tanhf(s * g_invn2);
    }
}

// #16: 2D partial rank counts for pool2 — split kernel (see #5 note)
__global__ void k_rank2a() {
    __shared__ float ss[KP1];
    for (int j = threadIdx.x; j < KP1; j += blockDim.x) ss[j] = g_score2[j];
    __syncthreads();
    int total = KP1 * 8;
    int stride = gridDim.x * blockDim.x;
    for (int w = blockIdx.x * blockDim.x + threadIdx.x; w < total; w += stride) {
        int i = w >> 3, ch = w & 7;
        float s = ss[i];
        int lo = ch * (KP1 / 8), hi = lo + KP1 / 8;
        int r = 0;
        for (int j = lo; j < hi; j++) {
            float v = ss[j];
            if (v > s) r++;
            else if (v == s && j < i) r++;
        }
        if (r) atomicAdd(&g_rk2[i], r);
    }
}

// #17: place
__global__ void k_rank2b() {
    int i = blockIdx.x * blockDim.x + threadIdx.x;
    if (i < KP1) {
        int r = g_rk2[i];
        if (r < KP2) { g_perm2[r] = i; g_sc2[r] = g_score2[i]; }
    }
}

// #18: FC (2048 blocks: f = b>>3, n-chunk = (b&7)*32) + fused cleanup
__global__ void __launch_bounds__(256) k_fc(const float* __restrict__ fcW,
                                            float* __restrict__ out) {
    __shared__ float sv[32];
    __shared__ float4 sacc[128];
    int b = blockIdx.x;
    int t = threadIdx.x;

    // ---- cleanup slice (dead data; next call's precondition) ----
    {
        const int CD = (N_NODES + 2047) / 2048;      // 49
        int o = b * CD;
        for (int i = t; i < CD && o + i < N_NODES; i += 256) {
            g_deg[o + i] = 0.f; g_map0[o + i] = 0; g_rk[o + i] = 0;
            g_agg4[o + i] = make_float4(0.f, 0.f, 0.f, 0.f);
        }
        if (t < 32) g_hist16[b * 32 + t] = 0u;
        if (t < 128) g_agg64[b * 128 + t] = 0.f;
        g_agg128[b * 256 + t] = 0.f;
        if (t < 2) { g_deg2x[b * 2 + t] = 0.f; g_rk2[b * 2 + t] = 0; }
        if (b == 0 && t < 2) { if (t == 0) g_ccount = 0; else g_e2cnt = 0; }
    }

    // ---- FC ----
    int f = b >> 3;
    int n0 = (b & 7) << 5;
    if (t < 32) {
        int n = n0 + t;
        sv[t] = g_x3[g_perm2[n] * 256 + f] * g_sc2[n];
    }
    __syncthreads();
    int sub = t >> 7, o4 = t & 127;
    const float4* fw = (const float4*)fcW;
    float4 acc = make_float4(0.f, 0.f, 0.f, 0.f);
    size_t base = ((size_t)(f * 256 + n0 + sub * 16)) * 128 + o4;
    #pragma unroll 16
    for (int j = 0; j < 16; j++) {
        float s = sv[sub * 16 + j];
        float4 w = __ldcs(&fw[base + (size_t)j * 128]);
        acc.x += s * w.x; acc.y += s * w.y; acc.z += s * w.z; acc.w += s * w.w;
    }
    if (sub == 1) sacc[o4] = acc;
    __syncthreads();
    if (sub == 0) {
        float4 o = sacc[o4];
        acc.x += o.x; acc.y += o.y; acc.z += o.z; acc.w += o.w;
        atomicAdd(((float4*)out) + o4, acc);
    }
}

// ---------------- launch ----------------
extern "C" void kernel_launch(void* const* d_in, const int* in_sizes, int n_in,
                              void* d_out, int out_size) {
    const float* pos = (const float*)d_in[0];
    const int*   ei  = (const int*)d_in[1];     // int32 (JAX default, no x64)
    const float* W1 = (const float*)d_in[2];
    const float* b1 = (const float*)d_in[3];
    const float* W2 = (const float*)d_in[4];
    const float* b2 = (const float*)d_in[5];
    const float* W3 = (const float*)d_in[6];
    const float* b3 = (const float*)d_in[7];
    const float* p1 = (const float*)d_in[8];
    const float* p2 = (const float*)d_in[9];
    const float* fcW = (const float*)d_in[10];
    const float* fcb = (const float*)d_in[11];
    float* out = (float*)d_out;

    const int EB = (N_EDGES + 255) / 256;
    const int NB = (N_NODES + 255) / 256;

    k_edge_deg<<<(N_EDGES / 2 + 255) / 256, 256>>>(ei);// 1
    k_prep<<<NB, 256>>>(pos, W1, b1, p1, p2, fcb, out);// 2
    k_agg3<<<EB, 256>>>(ei);                           // 3
    k_score1<<<12500, 256>>>(p1);                      // 4  <- profiled (warp/node)
    k_scan_a<<<256, 256>>>();                          // 5
    k_scan_b<<<1, 256>>>();                            // 6
    k_compact<<<NB, 256>>>();                          // 7
    k_rank1a<<<132, 256>>>();                          // 8
    k_place1<<<416, 256>>>();                          // 9
    k_ecompact<<<EB, 256>>>(ei);                       // 10
    k_escat64<<<512, 256>>>();                         // 11
    k_gemm2<<<128, 128>>>(W2, b2);                     // 12
    k_escat128<<<1024, 256>>>();                       // 13
    k_gemm3<<<256, 256>>>(W3, b3);                     // 14
    k_score2<<<512, 256>>>(p2);                        // 15
    k_rank2a<<<128, 256>>>();                          // 16
    k_rank2b<<<16, 256>>>();                           // 17
    k_fc<<<2048, 256>>>(fcW, out);                     // 18
}